// round 15
// baseline (speedup 1.0000x reference)
#include <cuda_runtime.h>
#include <cuda_fp16.h>
#include <cstdint>

// Decoder LSTM: B=128, H=1024, T=256, OUT=1, IN=2.
// Persistent kernel, 128 CTAs x 256 thr (8 warps).
// CTA (bg=cta>>6, ng=cta&63): batch rows [bg*64,+64) x hidden units [ng*16,+16)
// (64 gate rows of W_hh in SMEM fp16, 132KB).
// Warp (rtp 0..1, kq 0..3): 2 rt tiles x 64 N x k-quarter; one B ldsm feeds
// both rt tiles; each A block read exactly once.
// Tail split: warp kq=r does reduce+pointwise for tile r (4 active warps).
// Tree grid barrier (8 sub-counters -> root) per 64-CTA batch group.

#define NCTA 128
#define NTHR 256
#define HID 1024
#define BSZ 128
#define KP 1032   // padded K stride (fp16 elems) for W in SMEM

#define W_BYTES (64 * KP * 2)
#define CONST_BYTES 1024
#define RED_BYTES (2 * 2 * 3 * 8 * 32 * 16)
#define SMEM_BYTES (W_BYTES + CONST_BYTES + RED_BYTES)

// h in A-fragment layout (fp16x2): [rt 0..7][kt 0..63][lane 0..31][reg 0..3]
__device__ uint32_t g_frag[2][8 * 64 * 32 * 4];
__device__ unsigned int g_sub[2][8 * 32];   // tree barrier: 8 sub-counters/group
__device__ unsigned int g_root[2 * 32];
__device__ unsigned int g_gen[2 * 32];

__device__ __forceinline__ float sigf(float x) {
    return __fdividef(1.0f, 1.0f + __expf(-x));
}
__device__ __forceinline__ float tanh_f(float x) {
    return __fmaf_rn(2.0f, __fdividef(1.0f, 1.0f + __expf(-2.0f * x)), -1.0f);
}

__device__ __forceinline__ void mma_f16(float* c, const uint4& a, uint32_t b0, uint32_t b1) {
    asm volatile(
        "mma.sync.aligned.m16n8k16.row.col.f32.f16.f16.f32 "
        "{%0,%1,%2,%3},{%4,%5,%6,%7},{%8,%9},{%0,%1,%2,%3};\n"
        : "+f"(c[0]), "+f"(c[1]), "+f"(c[2]), "+f"(c[3])
        : "r"(a.x), "r"(a.y), "r"(a.z), "r"(a.w), "r"(b0), "r"(b1));
}

__device__ __forceinline__ void ldsm_x4(uint32_t& r0, uint32_t& r1, uint32_t& r2,
                                        uint32_t& r3, uint32_t saddr) {
    asm volatile("ldmatrix.sync.aligned.m8n8.x4.shared.b16 {%0,%1,%2,%3}, [%4];\n"
                 : "=r"(r0), "=r"(r1), "=r"(r2), "=r"(r3) : "r"(saddr));
}

__device__ __forceinline__ uint32_t packh2(float a, float b) {
    __half2 p = __floats2half2_rn(a, b);
    return *(uint32_t*)&p;
}

// two-level 64-CTA group barrier: 8 arrivals per sub-counter, 8 subs -> root
__device__ __forceinline__ void grid_barrier(int grp, int sub) {
    __threadfence();
    __syncthreads();
    if (threadIdx.x == 0) {
        volatile unsigned int* vgen = &g_gen[grp * 32];
        unsigned int g = *vgen;
        if (atomicAdd(&g_sub[grp][sub * 32], 1u) == 7u) {
            if (atomicAdd(&g_root[grp * 32], 1u) == 7u) {
#pragma unroll
                for (int s = 0; s < 8; ++s) g_sub[grp][s * 32] = 0u;
                g_root[grp * 32] = 0u;
                __threadfence();
                atomicExch((unsigned int*)&g_gen[grp * 32], g + 1u);
            }
        }
        while (*vgen == g) {}
        __threadfence();
    }
    __syncthreads();
}

extern __shared__ char smem_raw[];

__global__ __launch_bounds__(NTHR, 1) void decoder_kernel(
    const float* __restrict__ h0, const float* __restrict__ c0,
    const float* __restrict__ Wih, const float* __restrict__ Whh,
    const float* __restrict__ bih, const float* __restrict__ bhh,
    const float* __restrict__ Wlin, const float* __restrict__ blin,
    float* __restrict__ out, int T)
{
    __half* ws = (__half*)smem_raw;                       // [64][KP] W slice
    float* cc0 = (float*)(smem_raw + W_BYTES);            // bias (t=0)    [64]
    float* cc1 = cc0 + 64;                                // bias+Wih[:,1] [64]
    float* wi0 = cc1 + 64;                                // Wih[:,0]      [64]
    float* wl  = wi0 + 64;                                // Wlin slice    [16]
    float* red = (float*)(smem_raw + W_BYTES + CONST_BYTES);

    const int cta  = blockIdx.x;
    const int bg   = cta >> 6;       // batch half / barrier group
    const int ng   = cta & 63;       // hidden group (16 units)
    const int sub  = ng & 7;         // barrier sub-counter
    const int tid  = threadIdx.x;
    const int w    = tid >> 5;
    const int rtp  = w & 1;          // rt pair (2 tiles of 16 rows)
    const int kq   = w >> 1;         // k quarter; kq<2 also owns tile kq tail
    const int lane = tid & 31;
    const int gi   = lane >> 2;
    const int tq   = lane & 3;

    // ---------------- init: W slice (64 gate rows) -> SMEM fp16 ----------------
    for (int idx = tid; idx < 64 * HID; idx += NTHR) {
        int n = idx >> 10;
        int k = idx & (HID - 1);
        int row = ((n >> 4) << 10) + (ng << 4) + (n & 15);
        ws[n * KP + k] = __float2half_rn(Whh[row * HID + k]);
    }
    if (tid < 64) {
        int n = tid;
        int row = ((n >> 4) << 10) + (ng << 4) + (n & 15);
        float bb = bih[row] + bhh[row];
        cc0[n] = bb;
        cc1[n] = bb + Wih[row * 2 + 1];
        wi0[n] = Wih[row * 2 + 0];
    }
    if (tid < 16) wl[tid] = Wlin[(ng << 4) + tid];

    // h0 -> fragment buffer 0 (CTA c converts batch row c; same bg group)
    for (int p = tid; p < HID / 2; p += NTHR) {
        int k0 = p << 1;
        float a = h0[cta * HID + k0], b = h0[cta * HID + k0 + 1];
        int rtt = cta >> 4, kt = k0 >> 4;
        int lanep = (cta & 7) * 4 + ((k0 >> 1) & 3);
        int reg = ((cta >> 3) & 1) + 2 * ((k0 >> 3) & 1);
        g_frag[0][((rtt * 64 + kt) * 32 + lanep) * 4 + reg] = packh2(a, b);
    }
    for (int t = tid; t < T; t += NTHR) out[cta * T + t] = 0.0f;

    // rows: row(r, rh) = bg*64 + rtp*32 + r*16 + rh*8 + gi
    const int rowbase = bg * 64 + (rtp << 5);

    // creg for the tile this warp owns in the tail (kq < 2 -> tile r = kq)
    float creg[2][4] = {{0.f,0.f,0.f,0.f},{0.f,0.f,0.f,0.f}};
    if (kq < 2) {
#pragma unroll
        for (int rh = 0; rh < 2; ++rh)
#pragma unroll
            for (int q = 0; q < 4; ++q) {
                int u = (q >> 1) * 8 + (tq << 1) + (q & 1);
                creg[rh][q] =
                    c0[(rowbase + kq * 16 + rh * 8 + gi) * HID + (ng << 4) + u];
            }
    }
    const float blin0 = blin[0];

    // ldsm bases: group g2 covers W rows g2*16 .. +15 (n-tiles 2g2, 2g2+1)
    const int m_ = lane >> 3;
    const int r_ = lane & 7;
    const uint32_t s_w = (uint32_t)__cvta_generic_to_shared(ws);
    uint32_t sb[4];
#pragma unroll
    for (int g2 = 0; g2 < 4; ++g2) {
        int wrow = g2 * 16 + ((m_ >> 1) << 3) + r_;
        sb[g2] = s_w + (wrow * KP + ((m_ & 1) << 3)) * 2;
    }

    const int g_rt0  = bg * 4 + rtp * 2;                  // first global rt tile
    const int abase0 = g_rt0 * 8192 + (kq << 4) * 128 + lane * 4;
    const int abase1 = abase0 + 8192;

    // red block base (floats): block(r, pi) = ((rtp*2 + r)*3 + pi)*8
    // addr = ((block + nb)*32 + lane)*4
#define RED_ADDR(r, pi) (red + ((((rtp * 2 + (r)) * 3 + (pi)) * 8) * 32 + lane) * 4)

    grid_barrier(bg, sub);

    // ---------------- time loop ----------------
    for (int t = 0; t < T; ++t) {
        const uint32_t* A = g_frag[t & 1];
        uint32_t* N = g_frag[(t + 1) & 1];

        // acc{r}[nb][ci], nb = g*2 + uh, ci = rh*2 + p
        float acc0[8][4], acc1[8][4];
#pragma unroll
        for (int nb = 0; nb < 8; ++nb)
#pragma unroll
            for (int ci = 0; ci < 4; ++ci) { acc0[nb][ci] = 0.f; acc1[nb][ci] = 0.f; }

        if (kq < 2) {
            // bias + feedback init for the owned tile (r = kq)
            float op[2];
            const float* cc = cc0;
            if (t > 0) {
                op[0] = __ldcg(&out[(rowbase + kq * 16 + gi) * T + t - 1]);
                op[1] = __ldcg(&out[(rowbase + kq * 16 + 8 + gi) * T + t - 1]);
                cc = cc1;
            } else {
                op[0] = op[1] = 0.0f;
            }
            float (*accp)[4] = (kq == 0) ? acc0 : acc1;
#pragma unroll
            for (int nb = 0; nb < 8; ++nb) {
                int g = nb >> 1, uh = nb & 1;
#pragma unroll
                for (int ci = 0; ci < 4; ++ci) {
                    int p = ci & 1, rh = ci >> 1;
                    int n = g * 16 + uh * 8 + (tq << 1) + p;
                    accp[nb][ci] = fmaf(op[rh], wi0[n], cc[n]);
                }
            }
        }

        // GEMM: 16 k-iters, 2 rt tiles share each B load
#pragma unroll 4
        for (int i = 0; i < 16; ++i) {
            uint4 a0 = __ldcg((const uint4*)(A + abase0 + i * 128));
            uint4 a1 = __ldcg((const uint4*)(A + abase1 + i * 128));
            uint32_t so = ((kq << 4) + i) * 32;
#pragma unroll
            for (int g2 = 0; g2 < 4; ++g2) {
                uint32_t b0, b1, b2, b3;
                ldsm_x4(b0, b1, b2, b3, sb[g2] + so);
                mma_f16(acc0[2 * g2],     a0, b0, b1);
                mma_f16(acc0[2 * g2 + 1], a0, b2, b3);
                mma_f16(acc1[2 * g2],     a1, b0, b1);
                mma_f16(acc1[2 * g2 + 1], a1, b2, b3);
            }
        }

        // write partials: tile0 sourced by kq {1,2,3}, tile1 by kq {0,2,3}
        if (kq == 0) {
            float* d = RED_ADDR(1, 0);
#pragma unroll
            for (int nb = 0; nb < 8; ++nb) *(float4*)(d + nb * 128) = *(float4*)acc1[nb];
        } else if (kq == 1) {
            float* d = RED_ADDR(0, 0);
#pragma unroll
            for (int nb = 0; nb < 8; ++nb) *(float4*)(d + nb * 128) = *(float4*)acc0[nb];
        } else {
            float* d0 = RED_ADDR(0, kq - 1);
            float* d1 = RED_ADDR(1, kq - 1);
#pragma unroll
            for (int nb = 0; nb < 8; ++nb) {
                *(float4*)(d0 + nb * 128) = *(float4*)acc0[nb];
                *(float4*)(d1 + nb * 128) = *(float4*)acc1[nb];
            }
        }
        __syncthreads();

        if (kq < 2) {
            float (*accp)[4] = (kq == 0) ? acc0 : acc1;
#pragma unroll
            for (int pi = 0; pi < 3; ++pi) {
                const float* s = RED_ADDR(kq, pi);
#pragma unroll
                for (int nb = 0; nb < 8; ++nb) {
                    float4 x = *(const float4*)(s + nb * 128);
                    accp[nb][0] += x.x; accp[nb][1] += x.y;
                    accp[nb][2] += x.z; accp[nb][3] += x.w;
                }
            }

            // pointwise LSTM on owned tile (8 gate-sets/thread)
            float hv[2][4];
#pragma unroll
            for (int rh = 0; rh < 2; ++rh)
#pragma unroll
                for (int q = 0; q < 4; ++q) {
                    int uh = q >> 1, p = q & 1;
                    int ci = rh * 2 + p;
                    float cn = fmaf(sigf(accp[2 + uh][ci]), creg[rh][q],
                                    sigf(accp[0 + uh][ci]) * tanh_f(accp[4 + uh][ci]));
                    creg[rh][q] = cn;
                    hv[rh][q] = sigf(accp[6 + uh][ci]) * tanh_f(cn);
                }

            // h store: one STG.128 for the owned tile
            uint4 hp;
            hp.x = packh2(hv[0][0], hv[0][1]);
            hp.y = packh2(hv[1][0], hv[1][1]);
            hp.z = packh2(hv[0][2], hv[0][3]);
            hp.w = packh2(hv[1][2], hv[1][3]);
            *(uint4*)&N[(((g_rt0 + kq) * 64 + ng) * 32 + lane) * 4] = hp;

            // scalar head for the owned tile's 16 rows
#pragma unroll
            for (int rh = 0; rh < 2; ++rh) {
                float acc_s = 0.0f;
#pragma unroll
                for (int q = 0; q < 4; ++q) {
                    int u = (q >> 1) * 8 + (tq << 1) + (q & 1);
                    acc_s = fmaf(hv[rh][q], wl[u], acc_s);
                }
                acc_s += __shfl_xor_sync(0xffffffffu, acc_s, 1);
                acc_s += __shfl_xor_sync(0xffffffffu, acc_s, 2);
                if (tq == 0) {
                    if (ng == 0) acc_s += blin0;
                    atomicAdd(&out[(rowbase + kq * 16 + rh * 8 + gi) * T + t],
                              acc_s);
                }
            }
        }

        grid_barrier(bg, sub);
    }
#undef RED_ADDR
}

extern "C" void kernel_launch(void* const* d_in, const int* in_sizes, int n_in,
                              void* d_out, int out_size) {
    const float* h0   = (const float*)d_in[0];
    const float* c0   = (const float*)d_in[1];
    const float* Wih  = (const float*)d_in[2];
    const float* Whh  = (const float*)d_in[3];
    const float* bih  = (const float*)d_in[4];
    const float* bhh  = (const float*)d_in[5];
    const float* Wlin = (const float*)d_in[6];
    const float* blin = (const float*)d_in[7];
    float* out = (float*)d_out;

    int T = out_size / BSZ;
    if (T <= 0) return;

    cudaFuncSetAttribute(decoder_kernel,
                         cudaFuncAttributeMaxDynamicSharedMemorySize, SMEM_BYTES);
    decoder_kernel<<<NCTA, NTHR, SMEM_BYTES>>>(h0, c0, Wih, Whh, bih, bhh,
                                               Wlin, blin, out, T);
}